// round 14
// baseline (speedup 1.0000x reference)
#include <cuda_runtime.h>
#include <cuda_bf16.h>
#include <cuda_fp16.h>
#include <cstdint>

#define DINL __device__ __forceinline__

DINL uint32_t smem_u32(const void* p) {
    uint32_t a;
    asm("{ .reg .u64 t; cvta.to.shared.u64 t, %1; cvt.u32.u64 %0, t; }" : "=r"(a) : "l"(p));
    return a;
}
DINL void ldsm_x4(uint32_t r[4], uint32_t addr) {
    asm volatile("ldmatrix.sync.aligned.m8n8.x4.shared.b16 {%0,%1,%2,%3}, [%4];"
        : "=r"(r[0]), "=r"(r[1]), "=r"(r[2]), "=r"(r[3]) : "r"(addr));
}
DINL void ldsm_x2(uint32_t r[2], uint32_t addr) {
    asm volatile("ldmatrix.sync.aligned.m8n8.x2.shared.b16 {%0,%1}, [%2];"
        : "=r"(r[0]), "=r"(r[1]) : "r"(addr));
}
DINL void mma_bf16(float c[4], const uint32_t a[4], const uint32_t b[2]) {
    asm volatile("mma.sync.aligned.m16n8k16.row.col.f32.bf16.bf16.f32 "
        "{%0,%1,%2,%3}, {%4,%5,%6,%7}, {%8,%9}, {%0,%1,%2,%3};"
        : "+f"(c[0]), "+f"(c[1]), "+f"(c[2]), "+f"(c[3])
        : "r"(a[0]), "r"(a[1]), "r"(a[2]), "r"(a[3]), "r"(b[0]), "r"(b[1]));
}
DINL void mma_f16(float c[4], const uint32_t a[4], const uint32_t b[2]) {
    asm volatile("mma.sync.aligned.m16n8k16.row.col.f32.f16.f16.f32 "
        "{%0,%1,%2,%3}, {%4,%5,%6,%7}, {%8,%9}, {%0,%1,%2,%3};"
        : "+f"(c[0]), "+f"(c[1]), "+f"(c[2]), "+f"(c[3])
        : "r"(a[0]), "r"(a[1]), "r"(a[2]), "r"(a[3]), "r"(b[0]), "r"(b[1]));
}
#define STS64(a, v)  asm volatile("st.shared.b64 [%0], %1;" :: "r"(a), "l"(v) : "memory")
#define STS128(a, v) asm volatile("st.shared.v4.b32 [%0], {%1,%2,%3,%4};" \
    :: "r"(a), "r"((v).x), "r"((v).y), "r"((v).z), "r"((v).w) : "memory")
#define BAR_GRP(id) asm volatile("bar.sync %0, 128;" :: "r"(id) : "memory")
#define STG_CS_F2(p, vx, vy) asm volatile("st.global.cs.v2.f32 [%0], {%1,%2};" \
    :: "l"(p), "f"(vx), "f"(vy) : "memory")

DINL uint32_t pack2(float a, float b) {
    return ((uint32_t)__bfloat16_as_ushort(__float2bfloat16(b)) << 16)
         |  (uint32_t)__bfloat16_as_ushort(__float2bfloat16(a));
}
DINL uint64_t pack4(float a, float b, float c, float d) {
    return ((uint64_t)pack2(c, d) << 32) | (uint64_t)pack2(a, b);
}
DINL float rlo(float f) { return f - __bfloat162float(__float2bfloat16(f)); }
DINL uint32_t pack2h(float a, float b) {
    return ((uint32_t)__half_as_ushort(__float2half_rn(b)) << 16)
         |  (uint32_t)__half_as_ushort(__float2half_rn(a));
}

__device__ __align__(16) uint32_t g_w1h[8192];           // plain [n][kword] bf16x2
__device__ __align__(16) unsigned char g_w1l[32768];     // swizzled bf16
__device__ __align__(16) unsigned char g_w2h[32768];     // swizzled fp16 (single)
__device__ __align__(16) float g_b2[128];
static constexpr int IDX_CAP = 1 << 20;
__device__ int g_idxp[IDX_CAP];
static constexpr int H_CAP = 1 << 23;
__device__ __align__(16) __half g_Hh[H_CAP];             // H as single fp16

__global__ void prep_all(const float* __restrict__ W1, const float* __restrict__ W2,
                         const float* __restrict__ b2, const void* __restrict__ nbr_raw, int E) {
    __shared__ int s_is64;
    // ballot-based dtype sniff: threads 0-63 each check one high word
    if (threadIdx.x < 64) {
        const unsigned* w = (const unsigned*)nbr_raw;
        unsigned bad = __ballot_sync(0xffffffffu, w[2 * threadIdx.x + 1] != 0u);
        if ((threadIdx.x & 31) == 0) {
            if (threadIdx.x == 0) s_is64 = 1;
        }
        __syncwarp();
        if (threadIdx.x == 0 && bad) s_is64 = 0;
        if (threadIdx.x == 32 && bad) s_is64 = 0;
    }
    __syncthreads();
    const int is64 = s_is64;
    // 4 indices per thread
    const int base = (blockIdx.x * 256 + threadIdx.x) * 4;
#pragma unroll
    for (int q = 0; q < 4; q++) {
        const int i = base + q;
        if (i < E && i < IDX_CAP) {
            long long v = is64 ? ((const long long*)nbr_raw)[i]
                               : (long long)((const int*)nbr_raw)[i];
            g_idxp[i] = ((int)v) << 7;
        }
    }
    if (blockIdx.x == 0 && threadIdx.x < 128) g_b2[threadIdx.x] = b2[threadIdx.x];
    if (blockIdx.x < 128 && threadIdx.x < 128) {
        const int n = blockIdx.x, k = threadIdx.x;
        float w1e = W1[k * 128 + n] + W1[(k + 128) * 128 + n];   // fold concat
        float w2v = W2[k * 128 + n];
        __nv_bfloat16 h1 = __float2bfloat16(w1e);
        __nv_bfloat16 l1 = __float2bfloat16(w1e - __bfloat162float(h1));
        ((__nv_bfloat16*)g_w1h)[n * 128 + k] = h1;
        uint32_t ta = (uint32_t)(n * 256 + (((k >> 3) ^ (n & 7)) << 4) + ((k & 7) << 1));
        *(__nv_bfloat16*)(g_w1l + ta) = l1;
        *(__half*)(g_w2h + ta) = __float2half_rn(w2v);
    }
}

// ============ phase 1 (persistent): H = relu(x @ W1eff + b1), fp16 out ============
static constexpr int P1_W1L = 16384;
static constexpr int P1_B1  = 49152;
static constexpr int P1_SMEM = 49664;

__global__ void __launch_bounds__(256, 1)
prep_h(const float* __restrict__ x, const float* __restrict__ b1, int nodes) {
    extern __shared__ unsigned char sm[];
    const uint32_t sb = smem_u32(sm);
    const int tid = threadIdx.x, wid = tid >> 5, lane = tid & 31;

    {
        const uint4* s = (const uint4*)g_w1l;
        uint4* d = (uint4*)(sm + P1_W1L);
#pragma unroll
        for (int i = tid; i < 2048; i += 256) d[i] = s[i];
    }
    if (tid < 128) ((float*)(sm + P1_B1))[tid] = b1[tid];

    uint32_t B1h[2][8][2];
    {
        const int lc = lane & 3;
#pragma unroll
        for (int ch = 0; ch < 2; ch++) {
            const int nb = (wid * 16 + ch * 8 + (lane >> 2)) * 64;
#pragma unroll
            for (int ks = 0; ks < 8; ks++)
#pragma unroll
                for (int j = 0; j < 2; j++)
                    B1h[ch][ks][j] = g_w1h[nb + ks * 8 + j * 4 + lc];
        }
    }

    const int li = lane & 7, lg = lane >> 3;
    const int arow = ((lg & 1) << 3) + li;
    const int akh = lg >> 1;
    const uint32_t arowoff = (uint32_t)(arow * 256);
    const int arx = arow & 7;
    const int bg = lg & 1;
    const uint32_t bl_row0 = (uint32_t)((wid * 16 + li) * 256);
    const uint32_t bl_row1 = (uint32_t)((wid * 16 + 8 + li) * 256);
    const int blx0 = (wid * 16 + li) & 7, blx1 = (wid * 16 + 8 + li) & 7;
    const uint32_t W1Ls = sb + P1_W1L;
    const float* b1s = (const float*)(sm + P1_B1);

    const int ntiles = (nodes + 31) >> 5;
    for (int tile = blockIdx.x; tile < ntiles; tile += gridDim.x) {
        const int rb = tile << 5;
        __syncthreads();
        {
            const int r = tid >> 3, part = tid & 7;
            const bool ok = (rb + r) < nodes;
            const float4* xr = (const float4*)(x + (size_t)(rb + r) * 128 + part * 16);
#pragma unroll
            for (int i = 0; i < 4; i++) {
                float4 v = ok ? xr[i] : make_float4(0.f, 0.f, 0.f, 0.f);
                const int c0 = part * 16 + i * 4;
                const uint32_t a = (uint32_t)(r * 256 + (((c0 >> 3) ^ (r & 7)) << 4) + ((c0 & 7) << 1));
                STS64(sb + a, pack4(v.x, v.y, v.z, v.w));
                STS64(sb + 8192u + a, pack4(rlo(v.x), rlo(v.y), rlo(v.z), rlo(v.w)));
            }
        }
        __syncthreads();

        float acc[2][2][4] = {};
#pragma unroll
        for (int ks = 0; ks < 8; ks++) {
            uint32_t Bl0[2], Bl1[2];
            ldsm_x2(Bl0, W1Ls + bl_row0 + (uint32_t)((((ks << 1) + bg) ^ blx0) << 4));
            ldsm_x2(Bl1, W1Ls + bl_row1 + (uint32_t)((((ks << 1) + bg) ^ blx1) << 4));
            const uint32_t c = (uint32_t)((((ks << 1) + akh) ^ arx) << 4);
#pragma unroll
            for (int mf = 0; mf < 2; mf++) {
                uint32_t Ah[4], Al[4];
                ldsm_x4(Ah, sb + (uint32_t)(mf * 4096) + arowoff + c);
                ldsm_x4(Al, sb + 8192u + (uint32_t)(mf * 4096) + arowoff + c);
                mma_bf16(acc[mf][0], Ah, B1h[0][ks]);
                mma_bf16(acc[mf][1], Ah, B1h[1][ks]);
                mma_bf16(acc[mf][0], Ah, Bl0);
                mma_bf16(acc[mf][1], Ah, Bl1);
                mma_bf16(acc[mf][0], Al, B1h[0][ks]);
                mma_bf16(acc[mf][1], Al, B1h[1][ks]);
            }
        }

#pragma unroll
        for (int mf = 0; mf < 2; mf++) {
            const int gr0 = rb + mf * 16 + (lane >> 2), gr1 = gr0 + 8;
#pragma unroll
            for (int ch = 0; ch < 2; ch++) {
                const int col = wid * 16 + ch * 8 + (lane & 3) * 2;
                const float ba = b1s[col], bb = b1s[col + 1];
                const float f0 = fmaxf(acc[mf][ch][0] + ba, 0.f);
                const float f1 = fmaxf(acc[mf][ch][1] + bb, 0.f);
                const float f2 = fmaxf(acc[mf][ch][2] + ba, 0.f);
                const float f3 = fmaxf(acc[mf][ch][3] + bb, 0.f);
                if (gr0 < nodes)
                    *(uint32_t*)((char*)g_Hh + (size_t)gr0 * 256 + col * 2) = pack2h(f0, f1);
                if (gr1 < nodes)
                    *(uint32_t*)((char*)g_Hh + (size_t)gr1 * 256 + col * 2) = pack2h(f2, f3);
            }
        }
    }
}

// ============ phase 2: y = H[idx] @ W2 + b2, single-pass fp16, paired tiles ============
// SMEM: W2H sw [0,32K) | b2 [32K,32K+512) | groups at 33280: 4 x (A ring 4x8K = 32K)
static constexpr int P2_B2  = 32768;
static constexpr int P2_GRP = 33280;
static constexpr int P2_SMEM = 33280 + 4 * 32768;   // 164352

__global__ void __launch_bounds__(512, 1)
gs2_kernel(float* __restrict__ out, int E) {
    extern __shared__ unsigned char sm[];
    const uint32_t sb = smem_u32(sm);
    const int tid = threadIdx.x, wid = tid >> 5, lane = tid & 31;
    const int grp = wid >> 2, nw = wid & 3;

    {
        const uint4* sh = (const uint4*)g_w2h;
        uint4* dh = (uint4*)sm;
#pragma unroll
        for (int i = tid; i < 2048; i += 512) dh[i] = sh[i];
    }
    if (tid < 128) ((float*)(sm + P2_B2))[tid] = g_b2[tid];
    __syncthreads();

    const uint32_t W2H = sb;
    const uint32_t GB = sb + P2_GRP + (uint32_t)grp * 32768u;   // 4 slots of 8K
    const int barid = grp + 1;

    const int li = lane & 7, lg = lane >> 3;
    const int arow = ((lg & 1) << 3) + li;
    const int akh = lg >> 1;
    const uint32_t arowoff = (uint32_t)(arow * 256);
    const int arx = arow & 7;

    const int mi = lg;
    const int bkj = mi & 1;
    const int brow_a = nw * 32 + ((mi >> 1) << 3) + li;
    const int brow_b = brow_a + 16;
    const uint32_t boff_a = (uint32_t)(brow_a * 256);
    const uint32_t boff_b = (uint32_t)(brow_b * 256);
    const int brx_a = brow_a & 7, brx_b = brow_b & 7;

    const int grow0 = nw * 8 + (lane >> 4);
    const int gchunk = lane & 15;
    const int goff16 = gchunk * 16;
    uint32_t gadr[4];
#pragma unroll
    for (int q = 0; q < 4; q++) {
        const int r = grow0 + q * 2;
        gadr[q] = (uint32_t)(r * 256 + ((gchunk ^ (r & 7)) << 4));
    }
    const char* hbh = (const char*)g_Hh;

    const int ntiles = (E + 31) >> 5;
    const int g_abs = blockIdx.x * 4 + grp;
    const int stride = gridDim.x * 4;
    if (g_abs >= ntiles) return;

#define GLDG2(T, Q, VH) do {                                              \
        const int gr = ((T) << 5) + grow0 + (Q) * 2;                      \
        const int off = ((gr < E) ? g_idxp[gr] : 0) * 2 + goff16;         \
        VH = *(const uint4*)(hbh + off);                                  \
    } while (0)
#define GSTS2(BASE, Q, VH) STS128((BASE) + gadr[Q], VH)

    // preamble: gather first pair into slots 0,1
    {
        uint4 h0, h1, h2, h3;
        GLDG2(g_abs, 0, h0); GLDG2(g_abs, 1, h1);
        GLDG2(g_abs, 2, h2); GLDG2(g_abs, 3, h3);
        GSTS2(GB, 0, h0); GSTS2(GB, 1, h1);
        GSTS2(GB, 2, h2); GSTS2(GB, 3, h3);
        const int t1 = g_abs + stride;
        if (t1 < ntiles) {
            GLDG2(t1, 0, h0); GLDG2(t1, 1, h1);
            GLDG2(t1, 2, h2); GLDG2(t1, 3, h3);
            GSTS2(GB + 8192u, 0, h0); GSTS2(GB + 8192u, 1, h1);
            GSTS2(GB + 8192u, 2, h2); GSTS2(GB + 8192u, 3, h3);
        }
    }
    BAR_GRP(barid);

    const float* b2s = (const float*)(sm + P2_B2);

    for (int p = 0;; p++) {
        const int ta = g_abs + (2 * p) * stride;
        if (ta >= ntiles) break;
        const int tb = ta + stride;
        const bool hasB = (tb < ntiles);
        const uint32_t base_r = (uint32_t)((p & 1) * 2) * 8192u;
        const uint32_t base_w = (uint32_t)(((p + 1) & 1) * 2) * 8192u;
        const uint32_t AR_a = GB + base_r, AR_b = AR_a + 8192u;
        const uint32_t AW_a = GB + base_w, AW_b = AW_a + 8192u;
        const int na = ta + 2 * stride, nb = tb + 2 * stride;
        const bool hasNa = (na < ntiles), hasNb = (nb < ntiles);

        uint4 v0, v1, v2, v3;

        // ===== tile a =====
        {
            // gather LDG issued BEFORE the MMA loop: full-loop latency cover
            if (hasNa) {
                GLDG2(na, 0, v0); GLDG2(na, 1, v1);
                GLDG2(na, 2, v2); GLDG2(na, 3, v3);
            }
            float acc[2][4][4] = {};
#pragma unroll
            for (int ks = 0; ks < 8; ks++) {
                const uint32_t cka = (uint32_t)((((ks << 1) + bkj) ^ brx_a) << 4);
                const uint32_t ckb = (uint32_t)((((ks << 1) + bkj) ^ brx_b) << 4);
                uint32_t Bh01[4], Bh23[4];
                ldsm_x4(Bh01, W2H + boff_a + cka);
                ldsm_x4(Bh23, W2H + boff_b + ckb);
                const uint32_t c = (uint32_t)((((ks << 1) + akh) ^ arx) << 4);
#pragma unroll
                for (int mf = 0; mf < 2; mf++) {
                    uint32_t Ah[4];
                    ldsm_x4(Ah, AR_a + (uint32_t)(mf * 4096) + arowoff + c);
                    mma_f16(acc[mf][0], Ah, Bh01 + 0);
                    mma_f16(acc[mf][1], Ah, Bh01 + 2);
                    mma_f16(acc[mf][2], Ah, Bh23 + 0);
                    mma_f16(acc[mf][3], Ah, Bh23 + 2);
                }
            }
            // gather STS AFTER the MMA loop (LDG long complete)
            if (hasNa) {
                GSTS2(AW_a, 0, v0); GSTS2(AW_a, 1, v1);
                GSTS2(AW_a, 2, v2); GSTS2(AW_a, 3, v3);
            }
#pragma unroll
            for (int mf = 0; mf < 2; mf++) {
                const int rg0 = (ta << 5) + mf * 16 + (lane >> 2), rg1 = rg0 + 8;
#pragma unroll
                for (int cc = 0; cc < 4; cc++) {
                    const int col = nw * 32 + cc * 8 + (lane & 3) * 2;
                    const float ba = b2s[col], bb = b2s[col + 1];
                    if (rg0 < E) STG_CS_F2(out + (size_t)rg0 * 128 + col,
                                           acc[mf][cc][0] + ba, acc[mf][cc][1] + bb);
                    if (rg1 < E) STG_CS_F2(out + (size_t)rg1 * 128 + col,
                                           acc[mf][cc][2] + ba, acc[mf][cc][3] + bb);
                }
            }
        }

        // ===== tile b =====
        if (hasB) {
            if (hasNb) {
                GLDG2(nb, 0, v0); GLDG2(nb, 1, v1);
                GLDG2(nb, 2, v2); GLDG2(nb, 3, v3);
            }
            float acc[2][4][4] = {};
#pragma unroll
            for (int ks = 0; ks < 8; ks++) {
                const uint32_t cka = (uint32_t)((((ks << 1) + bkj) ^ brx_a) << 4);
                const uint32_t ckb = (uint32_t)((((ks << 1) + bkj) ^ brx_b) << 4);
                uint32_t Bh01[4], Bh23[4];
                ldsm_x4(Bh01, W2H + boff_a + cka);
                ldsm_x4(Bh23, W2H + boff_b + ckb);
                const uint32_t c = (uint32_t)((((ks << 1) + akh) ^ arx) << 4);
#pragma unroll
                for (int mf = 0; mf < 2; mf++) {
                    uint32_t Ah[4];
                    ldsm_x4(Ah, AR_b + (uint32_t)(mf * 4096) + arowoff + c);
                    mma_f16(acc[mf][0], Ah, Bh01 + 0);
                    mma_f16(acc[mf][1], Ah, Bh01 + 2);
                    mma_f16(acc[mf][2], Ah, Bh23 + 0);
                    mma_f16(acc[mf][3], Ah, Bh23 + 2);
                }
            }
            if (hasNb) {
                GSTS2(AW_b, 0, v0); GSTS2(AW_b, 1, v1);
                GSTS2(AW_b, 2, v2); GSTS2(AW_b, 3, v3);
            }
#pragma unroll
            for (int mf = 0; mf < 2; mf++) {
                const int rg0 = (tb << 5) + mf * 16 + (lane >> 2), rg1 = rg0 + 8;
#pragma unroll
                for (int cc = 0; cc < 4; cc++) {
                    const int col = nw * 32 + cc * 8 + (lane & 3) * 2;
                    const float ba = b2s[col], bb = b2s[col + 1];
                    if (rg0 < E) STG_CS_F2(out + (size_t)rg0 * 128 + col,
                                           acc[mf][cc][0] + ba, acc[mf][cc][1] + bb);
                    if (rg1 < E) STG_CS_F2(out + (size_t)rg1 * 128 + col,
                                           acc[mf][cc][2] + ba, acc[mf][cc][3] + bb);
                }
            }
        }

        BAR_GRP(barid);
    }
#undef GLDG2
#undef GSTS2
}

// ======================= launch =======================
extern "C" void kernel_launch(void* const* d_in, const int* in_sizes, int n_in,
                              void* d_out, int out_size) {
    const float* x  = (const float*)d_in[0];
    const void*  nb = d_in[1];
    const float* W1 = (const float*)d_in[2];
    const float* b1 = (const float*)d_in[3];
    const float* W2 = (const float*)d_in[4];
    const float* b2 = (const float*)d_in[5];
    float* out = (float*)d_out;
    const int E = in_sizes[1];
    const int nodes = in_sizes[0] / 128;

    int pg = (E + 1023) / 1024;   // 4 indices per thread
    if (pg < 128) pg = 128;
    prep_all<<<pg, 256>>>(W1, W2, b2, nb, E);

    int dev = 0;
    cudaGetDevice(&dev);
    int sms = 148;
    cudaDeviceGetAttribute(&sms, cudaDevAttrMultiProcessorCount, dev);

    const int ntiles1 = (nodes + 31) >> 5;
    int g1 = sms;
    if (g1 > ntiles1) g1 = ntiles1;
    cudaFuncSetAttribute(prep_h, cudaFuncAttributeMaxDynamicSharedMemorySize, P1_SMEM);
    prep_h<<<g1, 256, P1_SMEM>>>(x, b1, nodes);

    const int ntiles = (E + 31) >> 5;
    int grid = sms;
    const int maxg = (ntiles + 3) / 4;
    if (grid > maxg) grid = maxg;
    cudaFuncSetAttribute(gs2_kernel, cudaFuncAttributeMaxDynamicSharedMemorySize, P2_SMEM);
    gs2_kernel<<<grid, 512, P2_SMEM>>>(out, E);
}

// round 15
// speedup vs baseline: 1.0235x; 1.0235x over previous
#include <cuda_runtime.h>
#include <cuda_bf16.h>
#include <cuda_fp16.h>
#include <cstdint>

#define DINL __device__ __forceinline__

DINL uint32_t smem_u32(const void* p) {
    uint32_t a;
    asm("{ .reg .u64 t; cvta.to.shared.u64 t, %1; cvt.u32.u64 %0, t; }" : "=r"(a) : "l"(p));
    return a;
}
DINL void ldsm_x4(uint32_t r[4], uint32_t addr) {
    asm volatile("ldmatrix.sync.aligned.m8n8.x4.shared.b16 {%0,%1,%2,%3}, [%4];"
        : "=r"(r[0]), "=r"(r[1]), "=r"(r[2]), "=r"(r[3]) : "r"(addr));
}
DINL void ldsm_x2(uint32_t r[2], uint32_t addr) {
    asm volatile("ldmatrix.sync.aligned.m8n8.x2.shared.b16 {%0,%1}, [%2];"
        : "=r"(r[0]), "=r"(r[1]) : "r"(addr));
}
DINL void mma_bf16(float c[4], const uint32_t a[4], const uint32_t b[2]) {
    asm volatile("mma.sync.aligned.m16n8k16.row.col.f32.bf16.bf16.f32 "
        "{%0,%1,%2,%3}, {%4,%5,%6,%7}, {%8,%9}, {%0,%1,%2,%3};"
        : "+f"(c[0]), "+f"(c[1]), "+f"(c[2]), "+f"(c[3])
        : "r"(a[0]), "r"(a[1]), "r"(a[2]), "r"(a[3]), "r"(b[0]), "r"(b[1]));
}
DINL void mma_f16(float c[4], const uint32_t a[4], const uint32_t b[2]) {
    asm volatile("mma.sync.aligned.m16n8k16.row.col.f32.f16.f16.f32 "
        "{%0,%1,%2,%3}, {%4,%5,%6,%7}, {%8,%9}, {%0,%1,%2,%3};"
        : "+f"(c[0]), "+f"(c[1]), "+f"(c[2]), "+f"(c[3])
        : "r"(a[0]), "r"(a[1]), "r"(a[2]), "r"(a[3]), "r"(b[0]), "r"(b[1]));
}
#define STS64(a, v)  asm volatile("st.shared.b64 [%0], %1;" :: "r"(a), "l"(v) : "memory")
#define STS128(a, v) asm volatile("st.shared.v4.b32 [%0], {%1,%2,%3,%4};" \
    :: "r"(a), "r"((v).x), "r"((v).y), "r"((v).z), "r"((v).w) : "memory")
#define BAR_GRP(id) asm volatile("bar.sync %0, 128;" :: "r"(id) : "memory")
#define STG_CS_F2(p, vx, vy) asm volatile("st.global.cs.v2.f32 [%0], {%1,%2};" \
    :: "l"(p), "f"(vx), "f"(vy) : "memory")

DINL uint32_t pack2(float a, float b) {
    return ((uint32_t)__bfloat16_as_ushort(__float2bfloat16(b)) << 16)
         |  (uint32_t)__bfloat16_as_ushort(__float2bfloat16(a));
}
DINL uint64_t pack4(float a, float b, float c, float d) {
    return ((uint64_t)pack2(c, d) << 32) | (uint64_t)pack2(a, b);
}
DINL float rlo(float f) { return f - __bfloat162float(__float2bfloat16(f)); }
DINL uint32_t pack2h(float a, float b) {
    return ((uint32_t)__half_as_ushort(__float2half_rn(b)) << 16)
         |  (uint32_t)__half_as_ushort(__float2half_rn(a));
}

__device__ __align__(16) uint32_t g_w1h[8192];           // plain [n][kword] bf16x2
__device__ __align__(16) unsigned char g_w1l[32768];     // swizzled bf16
__device__ __align__(16) unsigned char g_w2h[32768];     // swizzled fp16 (single)
__device__ __align__(16) float g_b2[128];
__device__ int g_idx64;
static constexpr int H_CAP = 1 << 23;
__device__ __align__(16) __half g_Hh[H_CAP];             // H as single fp16

// ============ prologue: weights + dtype sniff only ============
__global__ void prep_all(const float* __restrict__ W1, const float* __restrict__ W2,
                         const float* __restrict__ b2, const void* __restrict__ nbr_raw) {
    if (blockIdx.x == 0 && threadIdx.x == 0) {
        const unsigned* w = (const unsigned*)nbr_raw;
        int is64 = 1;
        for (int i = 0; i < 64; i++)
            if (w[2 * i + 1] != 0u) { is64 = 0; break; }
        g_idx64 = is64;
    }
    if (blockIdx.x == 0 && threadIdx.x < 128) g_b2[threadIdx.x] = b2[threadIdx.x];
    const int n = blockIdx.x, k = threadIdx.x;
    float w1e = W1[k * 128 + n] + W1[(k + 128) * 128 + n];   // fold concat
    float w2v = W2[k * 128 + n];
    __nv_bfloat16 h1 = __float2bfloat16(w1e);
    __nv_bfloat16 l1 = __float2bfloat16(w1e - __bfloat162float(h1));
    ((__nv_bfloat16*)g_w1h)[n * 128 + k] = h1;
    uint32_t ta = (uint32_t)(n * 256 + (((k >> 3) ^ (n & 7)) << 4) + ((k & 7) << 1));
    *(__nv_bfloat16*)(g_w1l + ta) = l1;
    *(__half*)(g_w2h + ta) = __float2half_rn(w2v);
}

// ============ phase 1 (persistent, 2 CTA/SM): H = relu(x @ W1eff + b1) ============
static constexpr int P1_W1L = 16384;
static constexpr int P1_B1  = 49152;
static constexpr int P1_SMEM = 49664;

__global__ void __launch_bounds__(256, 2)
prep_h(const float* __restrict__ x, const float* __restrict__ b1, int nodes) {
    extern __shared__ unsigned char sm[];
    const uint32_t sb = smem_u32(sm);
    const int tid = threadIdx.x, wid = tid >> 5, lane = tid & 31;

    {
        const uint4* s = (const uint4*)g_w1l;
        uint4* d = (uint4*)(sm + P1_W1L);
#pragma unroll
        for (int i = tid; i < 2048; i += 256) d[i] = s[i];
    }
    if (tid < 128) ((float*)(sm + P1_B1))[tid] = b1[tid];

    uint32_t B1h[2][8][2];
    {
        const int lc = lane & 3;
#pragma unroll
        for (int ch = 0; ch < 2; ch++) {
            const int nb = (wid * 16 + ch * 8 + (lane >> 2)) * 64;
#pragma unroll
            for (int ks = 0; ks < 8; ks++)
#pragma unroll
                for (int j = 0; j < 2; j++)
                    B1h[ch][ks][j] = g_w1h[nb + ks * 8 + j * 4 + lc];
        }
    }

    const int li = lane & 7, lg = lane >> 3;
    const int arow = ((lg & 1) << 3) + li;
    const int akh = lg >> 1;
    const uint32_t arowoff = (uint32_t)(arow * 256);
    const int arx = arow & 7;
    const int bg = lg & 1;
    const uint32_t bl_row0 = (uint32_t)((wid * 16 + li) * 256);
    const uint32_t bl_row1 = (uint32_t)((wid * 16 + 8 + li) * 256);
    const int blx0 = (wid * 16 + li) & 7, blx1 = (wid * 16 + 8 + li) & 7;
    const uint32_t W1Ls = sb + P1_W1L;
    const float* b1s = (const float*)(sm + P1_B1);

    const int ntiles = (nodes + 31) >> 5;
    for (int tile = blockIdx.x; tile < ntiles; tile += gridDim.x) {
        const int rb = tile << 5;
        __syncthreads();
        {
            const int r = tid >> 3, part = tid & 7;
            const bool ok = (rb + r) < nodes;
            const float4* xr = (const float4*)(x + (size_t)(rb + r) * 128 + part * 16);
#pragma unroll
            for (int i = 0; i < 4; i++) {
                float4 v = ok ? xr[i] : make_float4(0.f, 0.f, 0.f, 0.f);
                const int c0 = part * 16 + i * 4;
                const uint32_t a = (uint32_t)(r * 256 + (((c0 >> 3) ^ (r & 7)) << 4) + ((c0 & 7) << 1));
                STS64(sb + a, pack4(v.x, v.y, v.z, v.w));
                STS64(sb + 8192u + a, pack4(rlo(v.x), rlo(v.y), rlo(v.z), rlo(v.w)));
            }
        }
        __syncthreads();

        float acc[2][2][4] = {};
#pragma unroll
        for (int ks = 0; ks < 8; ks++) {
            uint32_t Bl0[2], Bl1[2];
            ldsm_x2(Bl0, W1Ls + bl_row0 + (uint32_t)((((ks << 1) + bg) ^ blx0) << 4));
            ldsm_x2(Bl1, W1Ls + bl_row1 + (uint32_t)((((ks << 1) + bg) ^ blx1) << 4));
            const uint32_t c = (uint32_t)((((ks << 1) + akh) ^ arx) << 4);
#pragma unroll
            for (int mf = 0; mf < 2; mf++) {
                uint32_t Ah[4], Al[4];
                ldsm_x4(Ah, sb + (uint32_t)(mf * 4096) + arowoff + c);
                ldsm_x4(Al, sb + 8192u + (uint32_t)(mf * 4096) + arowoff + c);
                mma_bf16(acc[mf][0], Ah, B1h[0][ks]);
                mma_bf16(acc[mf][1], Ah, B1h[1][ks]);
                mma_bf16(acc[mf][0], Ah, Bl0);
                mma_bf16(acc[mf][1], Ah, Bl1);
                mma_bf16(acc[mf][0], Al, B1h[0][ks]);
                mma_bf16(acc[mf][1], Al, B1h[1][ks]);
            }
        }

#pragma unroll
        for (int mf = 0; mf < 2; mf++) {
            const int gr0 = rb + mf * 16 + (lane >> 2), gr1 = gr0 + 8;
#pragma unroll
            for (int ch = 0; ch < 2; ch++) {
                const int col = wid * 16 + ch * 8 + (lane & 3) * 2;
                const float ba = b1s[col], bb = b1s[col + 1];
                const float f0 = fmaxf(acc[mf][ch][0] + ba, 0.f);
                const float f1 = fmaxf(acc[mf][ch][1] + bb, 0.f);
                const float f2 = fmaxf(acc[mf][ch][2] + ba, 0.f);
                const float f3 = fmaxf(acc[mf][ch][3] + bb, 0.f);
                if (gr0 < nodes)
                    *(uint32_t*)((char*)g_Hh + (size_t)gr0 * 256 + col * 2) = pack2h(f0, f1);
                if (gr1 < nodes)
                    *(uint32_t*)((char*)g_Hh + (size_t)gr1 * 256 + col * 2) = pack2h(f2, f3);
            }
        }
    }
}

// ============ phase 2: y = H[idx] @ W2 + b2, single-pass fp16, paired tiles ============
// SMEM: W2H sw [0,32K) | b2 [32K,32K+512) | groups at 33280: 4 x (A ring 4x8K = 32K)
static constexpr int P2_B2  = 32768;
static constexpr int P2_GRP = 33280;
static constexpr int P2_SMEM = 33280 + 4 * 32768;   // 164352

__global__ void __launch_bounds__(512, 1)
gs2_kernel(const void* __restrict__ nbr_raw, float* __restrict__ out, int E) {
    extern __shared__ unsigned char sm[];
    const uint32_t sb = smem_u32(sm);
    const int tid = threadIdx.x, wid = tid >> 5, lane = tid & 31;
    const int grp = wid >> 2, nw = wid & 3;

    {
        const uint4* sh = (const uint4*)g_w2h;
        uint4* dh = (uint4*)sm;
#pragma unroll
        for (int i = tid; i < 2048; i += 512) dh[i] = sh[i];
    }
    if (tid < 128) ((float*)(sm + P2_B2))[tid] = g_b2[tid];
    __syncthreads();

    const uint32_t W2H = sb;
    const uint32_t GB = sb + P2_GRP + (uint32_t)grp * 32768u;   // 4 slots of 8K
    const int barid = grp + 1;

    const int li = lane & 7, lg = lane >> 3;
    const int arow = ((lg & 1) << 3) + li;
    const int akh = lg >> 1;
    const uint32_t arowoff = (uint32_t)(arow * 256);
    const int arx = arow & 7;

    const int mi = lg;
    const int bkj = mi & 1;
    const int brow_a = nw * 32 + ((mi >> 1) << 3) + li;
    const int brow_b = brow_a + 16;
    const uint32_t boff_a = (uint32_t)(brow_a * 256);
    const uint32_t boff_b = (uint32_t)(brow_b * 256);
    const int brx_a = brow_a & 7, brx_b = brow_b & 7;

    const int grow0 = nw * 8 + (lane >> 4);
    const int gchunk = lane & 15;
    const int goff16 = gchunk * 16;
    uint32_t gadr[4];
#pragma unroll
    for (int q = 0; q < 4; q++) {
        const int r = grow0 + q * 2;
        gadr[q] = (uint32_t)(r * 256 + ((gchunk ^ (r & 7)) << 4));
    }
    const char* hbh = (const char*)g_Hh;
    const int use64 = g_idx64;
    const long long* n64 = (const long long*)nbr_raw;
    const int* n32 = (const int*)nbr_raw;

    const int ntiles = (E + 31) >> 5;
    const int g_abs = blockIdx.x * 4 + grp;
    const int stride = gridDim.x * 4;
    if (g_abs >= ntiles) return;

#define GLDG2(T, Q, VH) do {                                              \
        const int gr = ((T) << 5) + grow0 + (Q) * 2;                      \
        const int grc = (gr < E) ? gr : 0;                                \
        const long long nd = use64 ? n64[grc] : (long long)n32[grc];      \
        VH = *(const uint4*)(hbh + ((size_t)nd << 8) + goff16);           \
    } while (0)
#define GSTS2(BASE, Q, VH) STS128((BASE) + gadr[Q], VH)

    // preamble: gather first pair into slots 0,1
    {
        uint4 h0, h1, h2, h3;
        GLDG2(g_abs, 0, h0); GLDG2(g_abs, 1, h1);
        GLDG2(g_abs, 2, h2); GLDG2(g_abs, 3, h3);
        GSTS2(GB, 0, h0); GSTS2(GB, 1, h1);
        GSTS2(GB, 2, h2); GSTS2(GB, 3, h3);
        const int t1 = g_abs + stride;
        if (t1 < ntiles) {
            GLDG2(t1, 0, h0); GLDG2(t1, 1, h1);
            GLDG2(t1, 2, h2); GLDG2(t1, 3, h3);
            GSTS2(GB + 8192u, 0, h0); GSTS2(GB + 8192u, 1, h1);
            GSTS2(GB + 8192u, 2, h2); GSTS2(GB + 8192u, 3, h3);
        }
    }
    BAR_GRP(barid);

    const float* b2s = (const float*)(sm + P2_B2);

    for (int p = 0;; p++) {
        const int ta = g_abs + (2 * p) * stride;
        if (ta >= ntiles) break;
        const int tb = ta + stride;
        const bool hasB = (tb < ntiles);
        const uint32_t base_r = (uint32_t)((p & 1) * 2) * 8192u;
        const uint32_t base_w = (uint32_t)(((p + 1) & 1) * 2) * 8192u;
        const uint32_t AR_a = GB + base_r, AR_b = AR_a + 8192u;
        const uint32_t AW_a = GB + base_w, AW_b = AW_a + 8192u;
        const int na = ta + 2 * stride, nb = tb + 2 * stride;
        const bool hasNa = (na < ntiles), hasNb = (nb < ntiles);

        uint4 v0, v1, v2, v3;

        // ===== tile a ===== (round-13 measured-best LDG/STS placement)
        {
            float acc[2][4][4] = {};
#pragma unroll
            for (int ks = 0; ks < 8; ks++) {
                if (ks == 2 && hasNa) {
                    GLDG2(na, 0, v0); GLDG2(na, 1, v1);
                    GLDG2(na, 2, v2); GLDG2(na, 3, v3);
                }
                if (ks == 5 && hasNa) {
                    GSTS2(AW_a, 0, v0); GSTS2(AW_a, 1, v1);
                    GSTS2(AW_a, 2, v2); GSTS2(AW_a, 3, v3);
                }
                const uint32_t cka = (uint32_t)((((ks << 1) + bkj) ^ brx_a) << 4);
                const uint32_t ckb = (uint32_t)((((ks << 1) + bkj) ^ brx_b) << 4);
                uint32_t Bh01[4], Bh23[4];
                ldsm_x4(Bh01, W2H + boff_a + cka);
                ldsm_x4(Bh23, W2H + boff_b + ckb);
                const uint32_t c = (uint32_t)((((ks << 1) + akh) ^ arx) << 4);
#pragma unroll
                for (int mf = 0; mf < 2; mf++) {
                    uint32_t Ah[4];
                    ldsm_x4(Ah, AR_a + (uint32_t)(mf * 4096) + arowoff + c);
                    mma_f16(acc[mf][0], Ah, Bh01 + 0);
                    mma_f16(acc[mf][1], Ah, Bh01 + 2);
                    mma_f16(acc[mf][2], Ah, Bh23 + 0);
                    mma_f16(acc[mf][3], Ah, Bh23 + 2);
                }
            }
#pragma unroll
            for (int mf = 0; mf < 2; mf++) {
                const int rg0 = (ta << 5) + mf * 16 + (lane >> 2), rg1 = rg0 + 8;
#pragma unroll
                for (int cc = 0; cc < 4; cc++) {
                    const int col = nw * 32 + cc * 8 + (lane & 3) * 2;
                    const float ba = b2s[col], bb = b2s[col + 1];
                    if (rg0 < E) STG_CS_F2(out + (size_t)rg0 * 128 + col,
                                           acc[mf][cc][0] + ba, acc[mf][cc][1] + bb);
                    if (rg1 < E) STG_CS_F2(out + (size_t)rg1 * 128 + col,
                                           acc[mf][cc][2] + ba, acc[mf][cc][3] + bb);
                }
            }
        }

        // ===== tile b =====
        if (hasB) {
            float acc[2][4][4] = {};
#pragma unroll
            for (int ks = 0; ks < 8; ks++) {
                if (ks == 2 && hasNb) {
                    GLDG2(nb, 0, v0); GLDG2(nb, 1, v1);
                    GLDG2(nb, 2, v2); GLDG2(nb, 3, v3);
                }
                if (ks == 5 && hasNb) {
                    GSTS2(AW_b, 0, v0); GSTS2(AW_b, 1, v1);
                    GSTS2(AW_b, 2, v2); GSTS2(AW_b, 3, v3);
                }
                const uint32_t cka = (uint32_t)((((ks << 1) + bkj) ^ brx_a) << 4);
                const uint32_t ckb = (uint32_t)((((ks << 1) + bkj) ^ brx_b) << 4);
                uint32_t Bh01[4], Bh23[4];
                ldsm_x4(Bh01, W2H + boff_a + cka);
                ldsm_x4(Bh23, W2H + boff_b + ckb);
                const uint32_t c = (uint32_t)((((ks << 1) + akh) ^ arx) << 4);
#pragma unroll
                for (int mf = 0; mf < 2; mf++) {
                    uint32_t Ah[4];
                    ldsm_x4(Ah, AR_b + (uint32_t)(mf * 4096) + arowoff + c);
                    mma_f16(acc[mf][0], Ah, Bh01 + 0);
                    mma_f16(acc[mf][1], Ah, Bh01 + 2);
                    mma_f16(acc[mf][2], Ah, Bh23 + 0);
                    mma_f16(acc[mf][3], Ah, Bh23 + 2);
                }
            }
#pragma unroll
            for (int mf = 0; mf < 2; mf++) {
                const int rg0 = (tb << 5) + mf * 16 + (lane >> 2), rg1 = rg0 + 8;
#pragma unroll
                for (int cc = 0; cc < 4; cc++) {
                    const int col = nw * 32 + cc * 8 + (lane & 3) * 2;
                    const float ba = b2s[col], bb = b2s[col + 1];
                    if (rg0 < E) STG_CS_F2(out + (size_t)rg0 * 128 + col,
                                           acc[mf][cc][0] + ba, acc[mf][cc][1] + bb);
                    if (rg1 < E) STG_CS_F2(out + (size_t)rg1 * 128 + col,
                                           acc[mf][cc][2] + ba, acc[mf][cc][3] + bb);
                }
            }
        }

        BAR_GRP(barid);
    }
#undef GLDG2
#undef GSTS2
}

// ======================= launch =======================
extern "C" void kernel_launch(void* const* d_in, const int* in_sizes, int n_in,
                              void* d_out, int out_size) {
    const float* x  = (const float*)d_in[0];
    const void*  nb = d_in[1];
    const float* W1 = (const float*)d_in[2];
    const float* b1 = (const float*)d_in[3];
    const float* W2 = (const float*)d_in[4];
    const float* b2 = (const float*)d_in[5];
    float* out = (float*)d_out;
    const int E = in_sizes[1];
    const int nodes = in_sizes[0] / 128;

    prep_all<<<128, 128>>>(W1, W2, b2, nb);

    int dev = 0;
    cudaGetDevice(&dev);
    int sms = 148;
    cudaDeviceGetAttribute(&sms, cudaDevAttrMultiProcessorCount, dev);

    const int ntiles1 = (nodes + 31) >> 5;
    int g1 = sms * 2;
    if (g1 > ntiles1) g1 = ntiles1;
    cudaFuncSetAttribute(prep_h, cudaFuncAttributeMaxDynamicSharedMemorySize, P1_SMEM);
    prep_h<<<g1, 256, P1_SMEM>>>(x, b1, nodes);

    const int ntiles = (E + 31) >> 5;
    int grid = sms;
    const int maxg = (ntiles + 3) / 4;
    if (grid > maxg) grid = maxg;
    cudaFuncSetAttribute(gs2_kernel, cudaFuncAttributeMaxDynamicSharedMemorySize, P2_SMEM);
    gs2_kernel<<<grid, 512, P2_SMEM>>>(nb, out, E);
}